// round 3
// baseline (speedup 1.0000x reference)
#include <cuda_runtime.h>
#include <math.h>
#include <stdint.h>
#include <stddef.h>

// ============================================================================
// NoisyTopkRouter: pre = h @ [Wl;Wn]^T  (fp32, FFMA2 SGEMM)  ->  scratch
//                  epilogue: softplus/noisy/softmax/top-k     ->  d_out
// Output layout assumed: [route_p (B*S*E) | ix-as-float (B*S*k) | full_p (B*S*E)]
// ============================================================================

#define BM 128
#define BK 16
#define SW (BM + 4)      // smem row stride (+4 pad: kills 4-way STS bank conflicts)
#define E_FIX 64

// 32768 tokens * 128 outputs (logits | noise-preact) fp32 scratch = 16 MB
__device__ float g_pre[32768 * 128];

typedef unsigned long long u64;

__device__ __forceinline__ u64 pack2(float lo, float hi) {
    u64 r;
    asm("mov.b64 %0, {%1, %2};" : "=l"(r) : "f"(lo), "f"(hi));
    return r;
}
__device__ __forceinline__ u64 ffma2(u64 a, u64 b, u64 c) {
    u64 d;
    asm("fma.rn.f32x2 %0, %1, %2, %3;" : "=l"(d) : "l"(a), "l"(b), "l"(c));
    return d;
}
__device__ __forceinline__ void unpack2(u64 v, float &lo, float &hi) {
    asm("mov.b64 {%0, %1}, %2;" : "=f"(lo), "=f"(hi) : "l"(v));
}

// ----------------------------------------------------------------------------
// GEMM: per CTA a [128 tokens x 128 outputs] tile, K = D, double-buffered smem,
// 8x8 microtile per thread, accumulators packed as f32x2 along N (FFMA2).
// B-matrix row n is Wl[n] for n < E, Wn[n-E] otherwise.
// ----------------------------------------------------------------------------
__global__ void __launch_bounds__(256, 2)
router_gemm(const float* __restrict__ h,
            const float* __restrict__ Wl,
            const float* __restrict__ Wn,
            int D, int E)
{
    __shared__ __align__(16) float As[2][BK][SW];
    __shared__ __align__(16) float Bs[2][BK][SW];

    const int tid = threadIdx.x;
    const int rowBase = blockIdx.x * BM;
    const int tx = tid & 15;        // -> n
    const int ty = tid >> 4;        // -> m
    const int m0 = ty * 8;
    const int n0 = tx * 8;

    // Global-load assignment: thread loads rows (lr, lr+64), float4 #kq of BK
    const int lr = tid >> 2;        // 0..63
    const int kq = tid & 3;         // 0..3
    const int kb = kq * 4;

    const float* aptr0 = h + (size_t)(rowBase + lr) * D + kb;
    const float* aptr1 = h + (size_t)(rowBase + lr + 64) * D + kb;
    const float* w0 = (lr < E) ? (Wl + (size_t)lr * D) : (Wn + (size_t)(lr - E) * D);
    const int lr2 = lr + 64;
    const float* w1 = (lr2 < E) ? (Wl + (size_t)lr2 * D) : (Wn + (size_t)(lr2 - E) * D);
    const float* bptr0 = w0 + kb;
    const float* bptr1 = w1 + kb;

    // ---- stage 0 ----
    {
        float4 a0 = *(const float4*)aptr0;
        float4 a1 = *(const float4*)aptr1;
        float4 b0 = *(const float4*)bptr0;
        float4 b1 = *(const float4*)bptr1;
        As[0][kb+0][lr] = a0.x; As[0][kb+1][lr] = a0.y; As[0][kb+2][lr] = a0.z; As[0][kb+3][lr] = a0.w;
        As[0][kb+0][lr+64] = a1.x; As[0][kb+1][lr+64] = a1.y; As[0][kb+2][lr+64] = a1.z; As[0][kb+3][lr+64] = a1.w;
        Bs[0][kb+0][lr] = b0.x; Bs[0][kb+1][lr] = b0.y; Bs[0][kb+2][lr] = b0.z; Bs[0][kb+3][lr] = b0.w;
        Bs[0][kb+0][lr+64] = b1.x; Bs[0][kb+1][lr+64] = b1.y; Bs[0][kb+2][lr+64] = b1.z; Bs[0][kb+3][lr+64] = b1.w;
    }
    __syncthreads();

    u64 acc[8][4];
#pragma unroll
    for (int i = 0; i < 8; ++i)
#pragma unroll
        for (int j = 0; j < 4; ++j) acc[i][j] = 0ull;

    const int NS = D / BK;
    for (int s = 0; s < NS; ++s) {
        const int cur = s & 1;
        float4 pa0, pa1, pb0, pb1;
        const bool more = (s + 1 < NS);
        if (more) {
            const int off = (s + 1) * BK;
            pa0 = *(const float4*)(aptr0 + off);
            pa1 = *(const float4*)(aptr1 + off);
            pb0 = *(const float4*)(bptr0 + off);
            pb1 = *(const float4*)(bptr1 + off);
        }
#pragma unroll
        for (int k = 0; k < BK; ++k) {
            float4 av0 = *(const float4*)&As[cur][k][m0];
            float4 av1 = *(const float4*)&As[cur][k][m0 + 4];
            float4 bv0 = *(const float4*)&Bs[cur][k][n0];
            float4 bv1 = *(const float4*)&Bs[cur][k][n0 + 4];
            u64 bb0 = pack2(bv0.x, bv0.y);
            u64 bb1 = pack2(bv0.z, bv0.w);
            u64 bb2 = pack2(bv1.x, bv1.y);
            u64 bb3 = pack2(bv1.z, bv1.w);
            float av[8] = {av0.x, av0.y, av0.z, av0.w, av1.x, av1.y, av1.z, av1.w};
#pragma unroll
            for (int i = 0; i < 8; ++i) {
                u64 ad = pack2(av[i], av[i]);
                acc[i][0] = ffma2(ad, bb0, acc[i][0]);
                acc[i][1] = ffma2(ad, bb1, acc[i][1]);
                acc[i][2] = ffma2(ad, bb2, acc[i][2]);
                acc[i][3] = ffma2(ad, bb3, acc[i][3]);
            }
        }
        if (more) {
            const int nxt = cur ^ 1;
            As[nxt][kb+0][lr] = pa0.x; As[nxt][kb+1][lr] = pa0.y; As[nxt][kb+2][lr] = pa0.z; As[nxt][kb+3][lr] = pa0.w;
            As[nxt][kb+0][lr+64] = pa1.x; As[nxt][kb+1][lr+64] = pa1.y; As[nxt][kb+2][lr+64] = pa1.z; As[nxt][kb+3][lr+64] = pa1.w;
            Bs[nxt][kb+0][lr] = pb0.x; Bs[nxt][kb+1][lr] = pb0.y; Bs[nxt][kb+2][lr] = pb0.z; Bs[nxt][kb+3][lr] = pb0.w;
            Bs[nxt][kb+0][lr+64] = pb1.x; Bs[nxt][kb+1][lr+64] = pb1.y; Bs[nxt][kb+2][lr+64] = pb1.z; Bs[nxt][kb+3][lr+64] = pb1.w;
        }
        __syncthreads();
    }

    const int NN = 2 * E;   // 128
#pragma unroll
    for (int i = 0; i < 8; ++i) {
        float4 lo, hi;
        unpack2(acc[i][0], lo.x, lo.y);
        unpack2(acc[i][1], lo.z, lo.w);
        unpack2(acc[i][2], hi.x, hi.y);
        unpack2(acc[i][3], hi.z, hi.w);
        float* dst = g_pre + (size_t)(rowBase + m0 + i) * NN + n0;
        *(float4*)dst = lo;
        *(float4*)(dst + 4) = hi;
    }
}

// ----------------------------------------------------------------------------
// Epilogue: one thread per token. Matches jax exactly:
//   std   = softplus(npre) = max(x,0) + log1p(exp(-|x|))
//   noisy = logits + noise*std
//   full_p = softmax(noisy); top-k (ties -> lower index, like lax.top_k);
//   route_p = softmax(where(topk, noisy, -1e30))  -> exact zeros off-topk.
// ----------------------------------------------------------------------------
__device__ __forceinline__ float softplus_f(float x) {
    return fmaxf(x, 0.0f) + log1pf(expf(-fabsf(x)));
}

__global__ void __launch_bounds__(128)
router_epilogue(const float* __restrict__ noise,
                const float* __restrict__ bl,
                const float* __restrict__ bn,
                float* __restrict__ out,
                int BS, int K)
{
    const int t = blockIdx.x * blockDim.x + threadIdx.x;
    if (t >= BS) return;
    const int E = E_FIX;
    const float* pre = g_pre + (size_t)t * (2 * E);
    const float* nz  = noise + (size_t)t * E;

    float noisy[E_FIX];
#pragma unroll
    for (int q = 0; q < E_FIX / 4; ++q) {
        float4 lg = *(const float4*)(pre + 4 * q);
        float4 np = *(const float4*)(pre + E + 4 * q);
        float4 ns = *(const float4*)(nz + 4 * q);
        float4 b0 = *(const float4*)(bl + 4 * q);
        float4 b1 = *(const float4*)(bn + 4 * q);
        noisy[4*q+0] = lg.x + b0.x + ns.x * softplus_f(np.x + b1.x);
        noisy[4*q+1] = lg.y + b0.y + ns.y * softplus_f(np.y + b1.y);
        noisy[4*q+2] = lg.z + b0.z + ns.z * softplus_f(np.z + b1.z);
        noisy[4*q+3] = lg.w + b0.w + ns.w * softplus_f(np.w + b1.w);
    }

    // max over all experts
    float m = noisy[0];
#pragma unroll
    for (int e = 1; e < E_FIX; ++e) m = fmaxf(m, noisy[e]);

    // top-K with strict '>' scan: ties resolve to the lowest index (lax.top_k)
    int   kidx[8];
    float kval[8];
    u64 chosen = 0ull;
    for (int j = 0; j < K; ++j) {
        float best = -INFINITY; int bi = 0;
#pragma unroll
        for (int e = 0; e < E_FIX; ++e) {
            bool ok = (((chosen >> e) & 1ull) == 0ull) && (noisy[e] > best);
            best = ok ? noisy[e] : best;
            bi   = ok ? e : bi;
        }
        kidx[j] = bi; kval[j] = best;
        chosen |= (1ull << bi);
    }

    // full softmax (overwrite noisy with exp values)
    float sum = 0.0f;
#pragma unroll
    for (int e = 0; e < E_FIX; ++e) {
        float x = expf(noisy[e] - m);
        noisy[e] = x;
        sum += x;
    }
    const float inv = 1.0f / sum;

    float* route = out + (size_t)t * E;
    float* ixo   = out + (size_t)BS * E + (size_t)t * K;
    float* fullp = out + (size_t)BS * E + (size_t)BS * K + (size_t)t * E;

#pragma unroll
    for (int q = 0; q < E_FIX / 4; ++q)
        *(float4*)(route + 4*q) = make_float4(0.f, 0.f, 0.f, 0.f);

    if (((((size_t)BS * (size_t)(E + K)) & 3) == 0)) {   // fullp 16B-aligned
#pragma unroll
        for (int q = 0; q < E_FIX / 4; ++q)
            *(float4*)(fullp + 4*q) = make_float4(noisy[4*q+0]*inv, noisy[4*q+1]*inv,
                                                  noisy[4*q+2]*inv, noisy[4*q+3]*inv);
    } else {
#pragma unroll
        for (int e = 0; e < E_FIX; ++e) fullp[e] = noisy[e] * inv;
    }

    // sparse (top-K) softmax: off-topk entries are exp(-1e30 - max) == 0 exactly
    const float rm = kval[0];
    float rs = 0.0f;
    float rv[8];
    for (int j = 0; j < K; ++j) { rv[j] = expf(kval[j] - rm); rs += rv[j]; }
    const float rinv = 1.0f / rs;
    for (int j = 0; j < K; ++j) {
        route[kidx[j]] = rv[j] * rinv;
        ixo[j] = (float)kidx[j];
    }
}

// ----------------------------------------------------------------------------
// Inputs (metadata order): h, Wl, bl, Wn, bn, noise, [top_k]
// ----------------------------------------------------------------------------
extern "C" void kernel_launch(void* const* d_in, const int* in_sizes, int n_in,
                              void* d_out, int out_size) {
    const float* h  = (const float*)d_in[0];
    const float* Wl = (const float*)d_in[1];
    const float* bl = (const float*)d_in[2];
    const float* Wn = (const float*)d_in[3];
    const float* bn = (const float*)d_in[4];
    const float* nz = (const float*)d_in[5];

    const int E = in_sizes[2];                     // 64
    const int D = in_sizes[1] / E;                 // 1024
    const long long BSE = (long long)in_sizes[5];  // B*S*E
    const int BS = (int)(BSE / E);                 // 32768

    // k derived from out_size = 2*B*S*E + B*S*k  (route_p | ix | full_p)
    int K = (int)(((long long)out_size - 2LL * BSE) / (long long)BS);
    if (K < 1 || K > 8) K = 2;

    router_gemm<<<BS / BM, 256>>>(h, Wl, Wn, D, E);
    router_epilogue<<<(BS + 127) / 128, 128>>>(nz, bl, bn, (float*)d_out, BS, K);
}